// round 2
// baseline (speedup 1.0000x reference)
#include <cuda_runtime.h>
#include <math.h>

// ---- problem dims ----
#define TT    2048      // tokens (B*S)
#define HD    2048      // hidden
#define ID    1408      // routed intermediate
#define ED    16        // experts
#define ISD   2816      // shared intermediate
#define CAPN  1024      // per-expert capacity (matches reference)

// ---- GEMM tile config ----
#define BM 128
#define BN 128
#define BK 16
#define TM 8
#define TN 8

// ---- device scratch (allocation-free per harness rules) ----
__device__ int   g_counts[ED];
__device__ int   g_slot_tok[ED * CAPN];
__device__ float g_slot_w[ED * CAPN];
__device__ float g_u_routed[(size_t)ED * CAPN * ID];   // ~92 MB
__device__ float g_h_routed[(size_t)ED * CAPN * ID];   // ~92 MB
__device__ float g_u_shared[(size_t)TT * ISD];         // ~23 MB
__device__ float g_h_shared[(size_t)TT * ISD];         // ~23 MB

__global__ void init_counts_kernel() {
    if (threadIdx.x < ED) g_counts[threadIdx.x] = 0;
}

// One block per token: 16 warps -> 16 expert logits, then softmax + top-2 + dispatch.
__global__ void router_kernel(const float* __restrict__ x, const float* __restrict__ gw) {
    int t = blockIdx.x;
    int warp = threadIdx.x >> 5, lane = threadIdx.x & 31;
    const float4* x4 = (const float4*)(x + (size_t)t * HD);
    const float4* w4 = (const float4*)(gw + (size_t)warp * HD);
    float acc = 0.f;
#pragma unroll 4
    for (int i = lane; i < HD / 4; i += 32) {
        float4 a = x4[i], b = w4[i];
        acc += a.x * b.x + a.y * b.y + a.z * b.z + a.w * b.w;
    }
#pragma unroll
    for (int o = 16; o > 0; o >>= 1) acc += __shfl_xor_sync(0xffffffffu, acc, o);
    __shared__ float logits[ED];
    if (lane == 0) logits[warp] = acc;
    __syncthreads();
    if (threadIdx.x == 0) {
        float mx = -1e30f;
        for (int e = 0; e < ED; e++) mx = fmaxf(mx, logits[e]);
        float s = 0.f, ex[ED];
        for (int e = 0; e < ED; e++) { ex[e] = expf(logits[e] - mx); s += ex[e]; }
        // greedy top-2; strict > keeps lowest index on ties (matches jax top_k)
        int i1 = 0; float v1 = logits[0];
        for (int e = 1; e < ED; e++) if (logits[e] > v1) { v1 = logits[e]; i1 = e; }
        int i2 = -1; float v2 = -1e30f;
        for (int e = 0; e < ED; e++) if (e != i1 && logits[e] > v2) { v2 = logits[e]; i2 = e; }
        float w1 = ex[i1] / s, w2 = ex[i2] / s;
        int s1 = atomicAdd(&g_counts[i1], 1);
        if (s1 < CAPN) { g_slot_tok[i1 * CAPN + s1] = t; g_slot_w[i1 * CAPN + s1] = w1; }
        int s2 = atomicAdd(&g_counts[i2], 1);
        if (s2 < CAPN) { g_slot_tok[i2 * CAPN + s2] = t; g_slot_w[i2 * CAPN + s2] = w2; }
    }
}

// Unified tiled GEMM. MODE:
//  0: shared up    : u_shared = x @ ws_up                      (M=TT, N=ISD, K=HD)
//  1: shared gate  : h_shared = silu(x @ ws_gate) * u_shared   (M=TT, N=ISD, K=HD)
//  2: shared down  : out      = h_shared @ ws_down  (plain store, full coverage)
//  3: routed up    : u_routed[e] = gather(x) @ w_up[e]         (M=cnt, N=ID, K=HD)
//  4: routed gate  : h_routed[e] = silu(.)*u_routed[e]
//  5: routed down  : out[token] += w * (h_routed[e] @ w_down[e])  (atomicAdd)
template <int MODE>
__global__ void __launch_bounds__(256, 2)
moe_gemm(const float* __restrict__ Aarg, const float* __restrict__ Barg,
         float* __restrict__ outArg)
{
    constexpr bool ROUTED = (MODE >= 3);
    constexpr bool GATHER = (MODE == 3 || MODE == 4);
    constexpr int N = (MODE <= 1) ? ISD : (MODE == 2 || MODE == 5) ? HD : ID;
    constexpr int K = (MODE <= 1) ? HD : (MODE == 2) ? ISD : (MODE == 5) ? ID : HD;

    const int e = ROUTED ? blockIdx.z : 0;
    int M;
    if (ROUTED) { M = g_counts[e]; if (M > CAPN) M = CAPN; } else M = TT;
    const int bm = blockIdx.y * BM;
    if (bm >= M) return;
    const int bn = blockIdx.x * BN;

    __shared__ float As[BK][BM];
    __shared__ float Bs[BK][BN];
    __shared__ int   stok[BM];
    __shared__ float swt[BM];

    const int tid = threadIdx.x;
    if (ROUTED) {
        if (tid < BM) {
            int r = bm + tid;
            stok[tid] = (r < M) ? g_slot_tok[e * CAPN + r] : 0;
            swt[tid]  = (r < M) ? g_slot_w[e * CAPN + r] : 0.f;
        }
        __syncthreads();
    }

    const float* Abase;
    if (MODE == 2)      Abase = g_h_shared;
    else if (MODE == 5) Abase = g_h_routed + (size_t)e * CAPN * ID;
    else                Abase = Aarg;
    const float* B = Barg + (ROUTED ? (size_t)e * HD * ID : (size_t)0);

    const int arow = tid >> 1;            // 0..127
    const int acol = (tid & 1) * 8;       // 0 or 8
    const int bkr  = tid >> 5;            // 0..7
    const int bcol = (tid & 31) * 4;      // 0..124
    const int tm   = (tid >> 4) * TM;
    const int tn   = (tid & 15) * TN;

    const float* Arowp;
    if (GATHER) Arowp = Aarg + (size_t)stok[arow] * HD;   // gather token row (safe fallback idx 0)
    else        Arowp = Abase + (size_t)(bm + arow) * K;  // always in-bounds (buffers sized to CAPN/TT)

    unsigned long long acc2[TM][TN / 2];
#pragma unroll
    for (int i = 0; i < TM; i++)
#pragma unroll
        for (int j = 0; j < TN / 2; j++) acc2[i][j] = 0ull;

    for (int k0 = 0; k0 < K; k0 += BK) {
        float4 a0 = *(const float4*)(Arowp + k0 + acol);
        float4 a1 = *(const float4*)(Arowp + k0 + acol + 4);
        const float* bp = B + (size_t)(k0 + bkr) * N + bn + bcol;
        float4 b0 = *(const float4*)bp;
        float4 b1 = *(const float4*)(bp + (size_t)8 * N);
        As[acol + 0][arow] = a0.x; As[acol + 1][arow] = a0.y;
        As[acol + 2][arow] = a0.z; As[acol + 3][arow] = a0.w;
        As[acol + 4][arow] = a1.x; As[acol + 5][arow] = a1.y;
        As[acol + 6][arow] = a1.z; As[acol + 7][arow] = a1.w;
        *(float4*)&Bs[bkr][bcol]     = b0;
        *(float4*)&Bs[bkr + 8][bcol] = b1;
        __syncthreads();
#pragma unroll
        for (int kk = 0; kk < BK; kk++) {
            float4 ra0 = *(const float4*)&As[kk][tm];
            float4 ra1 = *(const float4*)&As[kk][tm + 4];
            float ra[8] = {ra0.x, ra0.y, ra0.z, ra0.w, ra1.x, ra1.y, ra1.z, ra1.w};
            const unsigned long long* bsp = (const unsigned long long*)&Bs[kk][tn];
            unsigned long long rb0 = bsp[0], rb1 = bsp[1], rb2 = bsp[2], rb3 = bsp[3];
#pragma unroll
            for (int i = 0; i < TM; i++) {
                unsigned long long ai;
                asm("mov.b64 %0, {%1, %1};" : "=l"(ai) : "f"(ra[i]));
                asm("fma.rn.f32x2 %0, %1, %2, %0;" : "+l"(acc2[i][0]) : "l"(ai), "l"(rb0));
                asm("fma.rn.f32x2 %0, %1, %2, %0;" : "+l"(acc2[i][1]) : "l"(ai), "l"(rb1));
                asm("fma.rn.f32x2 %0, %1, %2, %0;" : "+l"(acc2[i][2]) : "l"(ai), "l"(rb2));
                asm("fma.rn.f32x2 %0, %1, %2, %0;" : "+l"(acc2[i][3]) : "l"(ai), "l"(rb3));
            }
        }
        __syncthreads();
    }

    // ---- epilogue ----
#pragma unroll
    for (int i = 0; i < TM; i++) {
        int m = bm + tm + i;
        if (m < M) {
#pragma unroll
            for (int j = 0; j < TN / 2; j++) {
                float lo, hi;
                asm("mov.b64 {%0, %1}, %2;" : "=f"(lo), "=f"(hi) : "l"(acc2[i][j]));
                size_t n = (size_t)(bn + tn + 2 * j);
                if (MODE == 0) {
                    *(float2*)&g_u_shared[(size_t)m * ISD + n] = make_float2(lo, hi);
                } else if (MODE == 1) {
                    float2 u = *(const float2*)&g_u_shared[(size_t)m * ISD + n];
                    float h0 = lo / (1.f + expf(-lo)) * u.x;
                    float h1 = hi / (1.f + expf(-hi)) * u.y;
                    *(float2*)&g_h_shared[(size_t)m * ISD + n] = make_float2(h0, h1);
                } else if (MODE == 2) {
                    *(float2*)&outArg[(size_t)m * HD + n] = make_float2(lo, hi);
                } else if (MODE == 3) {
                    *(float2*)&g_u_routed[((size_t)e * CAPN + m) * ID + n] = make_float2(lo, hi);
                } else if (MODE == 4) {
                    float2 u = *(const float2*)&g_u_routed[((size_t)e * CAPN + m) * ID + n];
                    float h0 = lo / (1.f + expf(-lo)) * u.x;
                    float h1 = hi / (1.f + expf(-hi)) * u.y;
                    *(float2*)&g_h_routed[((size_t)e * CAPN + m) * ID + n] = make_float2(h0, h1);
                } else {  // MODE 5: combine
                    int tok = stok[tm + i];
                    float wgt = swt[tm + i];
                    atomicAdd(&outArg[(size_t)tok * HD + n],     wgt * lo);
                    atomicAdd(&outArg[(size_t)tok * HD + n + 1], wgt * hi);
                }
            }
        }
    }
}

extern "C" void kernel_launch(void* const* d_in, const int* in_sizes, int n_in,
                              void* d_out, int out_size) {
    const float* x       = (const float*)d_in[0];  // [2,1024,2048]
    const float* gate_w  = (const float*)d_in[1];  // [16,2048]
    const float* w_gate  = (const float*)d_in[2];  // [16,2048,1408]
    const float* w_up    = (const float*)d_in[3];  // [16,2048,1408]
    const float* w_down  = (const float*)d_in[4];  // [16,1408,2048]
    const float* ws_gate = (const float*)d_in[5];  // [2048,2816]
    const float* ws_up   = (const float*)d_in[6];  // [2048,2816]
    const float* ws_down = (const float*)d_in[7];  // [2816,2048]
    float* out = (float*)d_out;                    // [2,1024,2048]

    init_counts_kernel<<<1, 32>>>();
    router_kernel<<<TT, 512>>>(x, gate_w);

    // shared-expert path (MODE 2 fully overwrites out — must precede routed atomics)
    moe_gemm<0><<<dim3(ISD / BN, TT / BM), 256>>>(x, ws_up, out);
    moe_gemm<1><<<dim3(ISD / BN, TT / BM), 256>>>(x, ws_gate, out);
    moe_gemm<2><<<dim3(HD / BN, TT / BM), 256>>>(x, ws_down, out);

    // routed-expert path
    moe_gemm<3><<<dim3(ID / BN, CAPN / BM, ED), 256>>>(x, w_up, out);
    moe_gemm<4><<<dim3(ID / BN, CAPN / BM, ED), 256>>>(x, w_gate, out);
    moe_gemm<5><<<dim3(HD / BN, CAPN / BM, ED), 256>>>(x, w_down, out);
}

// round 5
// speedup vs baseline: 1.0024x; 1.0024x over previous
#include <cuda_runtime.h>
#include <math.h>

// ---- problem dims ----
#define TT    2048      // tokens (B*S)
#define HD    2048      // hidden
#define ID    1408      // routed intermediate
#define ED    16        // experts
#define ISD   2816      // shared intermediate
#define CAPN  1024      // per-expert capacity (matches reference)

// ---- GEMM tile config ----
#define BM 128
#define BN 128
#define BK 16
#define TM 8
#define TN 8

// ---- device scratch (allocation-free per harness rules) ----
__device__ int   g_counts[ED];
__device__ int   g_slot_tok[ED * CAPN];
__device__ float g_slot_w[ED * CAPN];
__device__ float g_u_routed[(size_t)ED * CAPN * ID];   // ~92 MB
__device__ float g_h_routed[(size_t)ED * CAPN * ID];   // ~92 MB
__device__ float g_u_shared[(size_t)TT * ISD];         // ~23 MB
__device__ float g_h_shared[(size_t)TT * ISD];         // ~23 MB

__global__ void init_counts_kernel() {
    if (threadIdx.x < ED) g_counts[threadIdx.x] = 0;
}

// One block per token: 16 warps -> 16 expert logits, then softmax + top-2 + dispatch.
__global__ void router_kernel(const float* __restrict__ x, const float* __restrict__ gw) {
    int t = blockIdx.x;
    int warp = threadIdx.x >> 5, lane = threadIdx.x & 31;
    const float4* x4 = (const float4*)(x + (size_t)t * HD);
    const float4* w4 = (const float4*)(gw + (size_t)warp * HD);
    float acc = 0.f;
#pragma unroll 4
    for (int i = lane; i < HD / 4; i += 32) {
        float4 a = x4[i], b = w4[i];
        acc += a.x * b.x + a.y * b.y + a.z * b.z + a.w * b.w;
    }
#pragma unroll
    for (int o = 16; o > 0; o >>= 1) acc += __shfl_xor_sync(0xffffffffu, acc, o);
    __shared__ float logits[ED];
    if (lane == 0) logits[warp] = acc;
    __syncthreads();
    if (threadIdx.x == 0) {
        float mx = -1e30f;
        for (int e = 0; e < ED; e++) mx = fmaxf(mx, logits[e]);
        float s = 0.f, ex[ED];
        for (int e = 0; e < ED; e++) { ex[e] = expf(logits[e] - mx); s += ex[e]; }
        // greedy top-2; strict > keeps lowest index on ties (matches jax top_k)
        int i1 = 0; float v1 = logits[0];
        for (int e = 1; e < ED; e++) if (logits[e] > v1) { v1 = logits[e]; i1 = e; }
        int i2 = -1; float v2 = -1e30f;
        for (int e = 0; e < ED; e++) if (e != i1 && logits[e] > v2) { v2 = logits[e]; i2 = e; }
        float w1 = ex[i1] / s, w2 = ex[i2] / s;
        int s1 = atomicAdd(&g_counts[i1], 1);
        if (s1 < CAPN) { g_slot_tok[i1 * CAPN + s1] = t; g_slot_w[i1 * CAPN + s1] = w1; }
        int s2 = atomicAdd(&g_counts[i2], 1);
        if (s2 < CAPN) { g_slot_tok[i2 * CAPN + s2] = t; g_slot_w[i2 * CAPN + s2] = w2; }
    }
}

// Unified tiled GEMM. MODE:
//  0: shared up    : u_shared = x @ ws_up                      (M=TT, N=ISD, K=HD)
//  1: shared gate  : h_shared = silu(x @ ws_gate) * u_shared   (M=TT, N=ISD, K=HD)
//  2: shared down  : out      = h_shared @ ws_down  (plain store, full coverage)
//  3: routed up    : u_routed[e] = gather(x) @ w_up[e]         (M=cnt, N=ID, K=HD)
//  4: routed gate  : h_routed[e] = silu(.)*u_routed[e]
//  5: routed down  : out[token] += w * (h_routed[e] @ w_down[e])  (atomicAdd)
template <int MODE>
__global__ void __launch_bounds__(256, 2)
moe_gemm(const float* __restrict__ Aarg, const float* __restrict__ Barg,
         float* __restrict__ outArg)
{
    constexpr bool ROUTED = (MODE >= 3);
    constexpr bool GATHER = (MODE == 3 || MODE == 4);
    constexpr int N = (MODE <= 1) ? ISD : (MODE == 2 || MODE == 5) ? HD : ID;
    constexpr int K = (MODE <= 1) ? HD : (MODE == 2) ? ISD : (MODE == 5) ? ID : HD;

    const int e = ROUTED ? blockIdx.z : 0;
    int M;
    if (ROUTED) { M = g_counts[e]; if (M > CAPN) M = CAPN; } else M = TT;
    const int bm = blockIdx.y * BM;
    if (bm >= M) return;
    const int bn = blockIdx.x * BN;

    __shared__ float As[BK][BM];
    __shared__ float Bs[BK][BN];
    __shared__ int   stok[BM];
    __shared__ float swt[BM];

    const int tid = threadIdx.x;
    if (ROUTED) {
        if (tid < BM) {
            int r = bm + tid;
            stok[tid] = (r < M) ? g_slot_tok[e * CAPN + r] : 0;
            swt[tid]  = (r < M) ? g_slot_w[e * CAPN + r] : 0.f;
        }
        __syncthreads();
    }

    const float* Abase;
    if (MODE == 2)      Abase = g_h_shared;
    else if (MODE == 5) Abase = g_h_routed + (size_t)e * CAPN * ID;
    else                Abase = Aarg;
    const float* B = Barg + (ROUTED ? (size_t)e * HD * ID : (size_t)0);

    const int arow = tid >> 1;            // 0..127
    const int acol = (tid & 1) * 8;       // 0 or 8
    const int bkr  = tid >> 5;            // 0..7
    const int bcol = (tid & 31) * 4;      // 0..124
    const int tm   = (tid >> 4) * TM;
    const int tn   = (tid & 15) * TN;

    const float* Arowp;
    if (GATHER) Arowp = Aarg + (size_t)stok[arow] * HD;   // gather token row (safe fallback idx 0)
    else        Arowp = Abase + (size_t)(bm + arow) * K;  // always in-bounds (buffers sized to CAPN/TT)

    unsigned long long acc2[TM][TN / 2];
#pragma unroll
    for (int i = 0; i < TM; i++)
#pragma unroll
        for (int j = 0; j < TN / 2; j++) acc2[i][j] = 0ull;

    for (int k0 = 0; k0 < K; k0 += BK) {
        float4 a0 = *(const float4*)(Arowp + k0 + acol);
        float4 a1 = *(const float4*)(Arowp + k0 + acol + 4);
        const float* bp = B + (size_t)(k0 + bkr) * N + bn + bcol;
        float4 b0 = *(const float4*)bp;
        float4 b1 = *(const float4*)(bp + (size_t)8 * N);
        As[acol + 0][arow] = a0.x; As[acol + 1][arow] = a0.y;
        As[acol + 2][arow] = a0.z; As[acol + 3][arow] = a0.w;
        As[acol + 4][arow] = a1.x; As[acol + 5][arow] = a1.y;
        As[acol + 6][arow] = a1.z; As[acol + 7][arow] = a1.w;
        *(float4*)&Bs[bkr][bcol]     = b0;
        *(float4*)&Bs[bkr + 8][bcol] = b1;
        __syncthreads();
#pragma unroll
        for (int kk = 0; kk < BK; kk++) {
            float4 ra0 = *(const float4*)&As[kk][tm];
            float4 ra1 = *(const float4*)&As[kk][tm + 4];
            float ra[8] = {ra0.x, ra0.y, ra0.z, ra0.w, ra1.x, ra1.y, ra1.z, ra1.w};
            const unsigned long long* bsp = (const unsigned long long*)&Bs[kk][tn];
            unsigned long long rb0 = bsp[0], rb1 = bsp[1], rb2 = bsp[2], rb3 = bsp[3];
#pragma unroll
            for (int i = 0; i < TM; i++) {
                unsigned long long ai;
                asm("mov.b64 %0, {%1, %1};" : "=l"(ai) : "f"(ra[i]));
                asm("fma.rn.f32x2 %0, %1, %2, %0;" : "+l"(acc2[i][0]) : "l"(ai), "l"(rb0));
                asm("fma.rn.f32x2 %0, %1, %2, %0;" : "+l"(acc2[i][1]) : "l"(ai), "l"(rb1));
                asm("fma.rn.f32x2 %0, %1, %2, %0;" : "+l"(acc2[i][2]) : "l"(ai), "l"(rb2));
                asm("fma.rn.f32x2 %0, %1, %2, %0;" : "+l"(acc2[i][3]) : "l"(ai), "l"(rb3));
            }
        }
        __syncthreads();
    }

    // ---- epilogue ----
#pragma unroll
    for (int i = 0; i < TM; i++) {
        int m = bm + tm + i;
        if (m < M) {
#pragma unroll
            for (int j = 0; j < TN / 2; j++) {
                float lo, hi;
                asm("mov.b64 {%0, %1}, %2;" : "=f"(lo), "=f"(hi) : "l"(acc2[i][j]));
                size_t n = (size_t)(bn + tn + 2 * j);
                if (MODE == 0) {
                    *(float2*)&g_u_shared[(size_t)m * ISD + n] = make_float2(lo, hi);
                } else if (MODE == 1) {
                    float2 u = *(const float2*)&g_u_shared[(size_t)m * ISD + n];
                    float h0 = lo / (1.f + expf(-lo)) * u.x;
                    float h1 = hi / (1.f + expf(-hi)) * u.y;
                    *(float2*)&g_h_shared[(size_t)m * ISD + n] = make_float2(h0, h1);
                } else if (MODE == 2) {
                    *(float2*)&outArg[(size_t)m * HD + n] = make_float2(lo, hi);
                } else if (MODE == 3) {
                    *(float2*)&g_u_routed[((size_t)e * CAPN + m) * ID + n] = make_float2(lo, hi);
                } else if (MODE == 4) {
                    float2 u = *(const float2*)&g_u_routed[((size_t)e * CAPN + m) * ID + n];
                    float h0 = lo / (1.f + expf(-lo)) * u.x;
                    float h1 = hi / (1.f + expf(-hi)) * u.y;
                    *(float2*)&g_h_routed[((size_t)e * CAPN + m) * ID + n] = make_float2(h0, h1);
                } else {  // MODE 5: combine
                    int tok = stok[tm + i];
                    float wgt = swt[tm + i];
                    atomicAdd(&outArg[(size_t)tok * HD + n],     wgt * lo);
                    atomicAdd(&outArg[(size_t)tok * HD + n + 1], wgt * hi);
                }
            }
        }
    }
}

extern "C" void kernel_launch(void* const* d_in, const int* in_sizes, int n_in,
                              void* d_out, int out_size) {
    const float* x       = (const float*)d_in[0];  // [2,1024,2048]
    const float* gate_w  = (const float*)d_in[1];  // [16,2048]
    const float* w_gate  = (const float*)d_in[2];  // [16,2048,1408]
    const float* w_up    = (const float*)d_in[3];  // [16,2048,1408]
    const float* w_down  = (const float*)d_in[4];  // [16,1408,2048]
    const float* ws_gate = (const float*)d_in[5];  // [2048,2816]
    const float* ws_up   = (const float*)d_in[6];  // [2048,2816]
    const float* ws_down = (const float*)d_in[7];  // [2816,2048]
    float* out = (float*)d_out;                    // [2,1024,2048]

    init_counts_kernel<<<1, 32>>>();
    router_kernel<<<TT, 512>>>(x, gate_w);

    // shared-expert path (MODE 2 fully overwrites out — must precede routed atomics)
    moe_gemm<0><<<dim3(ISD / BN, TT / BM), 256>>>(x, ws_up, out);
    moe_gemm<1><<<dim3(ISD / BN, TT / BM), 256>>>(x, ws_gate, out);
    moe_gemm<2><<<dim3(HD / BN, TT / BM), 256>>>(x, ws_down, out);

    // routed-expert path
    moe_gemm<3><<<dim3(ID / BN, CAPN / BM, ED), 256>>>(x, w_up, out);
    moe_gemm<4><<<dim3(ID / BN, CAPN / BM, ED), 256>>>(x, w_gate, out);
    moe_gemm<5><<<dim3(HD / BN, CAPN / BM, ED), 256>>>(x, w_down, out);
}

// round 13
// speedup vs baseline: 2.2864x; 2.2810x over previous
#include <cuda_runtime.h>
#include <cuda_bf16.h>
#include <math.h>
#include <stdint.h>

#define TT    2048
#define HD    2048
#define ID    1408
#define ED    16
#define ISD   2816
#define CAPN  1024

__device__ int   g_counts[ED];
__device__ int   g_slot_tok[ED * CAPN];
__device__ float g_slot_w[ED * CAPN];
__device__ float g_u_shared[(size_t)TT * ISD];
__device__ float g_h_shared[(size_t)TT * ISD];
__device__ float g_u_routed[(size_t)ED * CAPN * ID];
__device__ float g_h_routed[(size_t)ED * CAPN * ID];

#define ASTRIDE_B 80
#define BSTRIDE_B 272
#define AHI 0
#define ALO 10240
#define BHI 20480
#define BLO 29184
#define STAGE 37888
#define DSMEM (2 * STAGE)

__device__ __forceinline__ uint32_t smem_u32(const void* p) {
    uint32_t a;
    asm("{ .reg .u64 t; cvta.to.shared.u64 t, %1; cvt.u32.u64 %0, t; }" : "=r"(a) : "l"(p));
    return a;
}
__device__ __forceinline__ void sts128(uint32_t a, uint32_t x, uint32_t y, uint32_t z, uint32_t w) {
    asm volatile("st.shared.v4.b32 [%0], {%1, %2, %3, %4};" :: "r"(a), "r"(x), "r"(y), "r"(z), "r"(w) : "memory");
}
__device__ __forceinline__ void cvt_hilo(float a, float b, uint32_t& h, uint32_t& l) {
    __nv_bfloat162 hh = __floats2bfloat162_rn(a, b);
    __nv_bfloat162 ll = __floats2bfloat162_rn(a - __bfloat162float(hh.x),
                                              b - __bfloat162float(hh.y));
    h = *(uint32_t*)&hh; l = *(uint32_t*)&ll;
}

#define LDSM_X4(r, a) \
    asm volatile("ldmatrix.sync.aligned.m8n8.x4.shared.b16 {%0,%1,%2,%3}, [%4];" \
        : "=r"((r)[0]), "=r"((r)[1]), "=r"((r)[2]), "=r"((r)[3]) : "r"(a))
#define LDSM_X4T(r0, r1, r2, r3, a) \
    asm volatile("ldmatrix.sync.aligned.m8n8.x4.trans.shared.b16 {%0,%1,%2,%3}, [%4];" \
        : "=r"(r0), "=r"(r1), "=r"(r2), "=r"(r3) : "r"(a))
#define MMA_BF16(d, a, b0, b1) \
    asm volatile("mma.sync.aligned.m16n8k16.row.col.f32.bf16.bf16.f32 " \
        "{%0,%1,%2,%3}, {%4,%5,%6,%7}, {%8,%9}, {%0,%1,%2,%3};" \
        : "+f"((d)[0]), "+f"((d)[1]), "+f"((d)[2]), "+f"((d)[3]) \
        : "r"((a)[0]), "r"((a)[1]), "r"((a)[2]), "r"((a)[3]), "r"(b0), "r"(b1))

__global__ void init_counts_kernel() {
    if (threadIdx.x < ED) g_counts[threadIdx.x] = 0;
}

__global__ void router_kernel(const float* __restrict__ x, const float* __restrict__ gw) {
    int t = blockIdx.x;
    int warp = threadIdx.x >> 5, lane = threadIdx.x & 31;
    const float4* x4 = (const float4*)(x + (size_t)t * HD);
    const float4* w4 = (const float4*)(gw + (size_t)warp * HD);
    float acc = 0.f;
#pragma unroll 4
    for (int i = lane; i < HD / 4; i += 32) {
        float4 a = x4[i], b = w4[i];
        acc += a.x * b.x + a.y * b.y + a.z * b.z + a.w * b.w;
    }
#pragma unroll
    for (int o = 16; o > 0; o >>= 1) acc += __shfl_xor_sync(0xffffffffu, acc, o);
    __shared__ float logits[ED];
    if (lane == 0) logits[warp] = acc;
    __syncthreads();
    if (threadIdx.x == 0) {
        float mx = -1e30f;
        for (int e = 0; e < ED; e++) mx = fmaxf(mx, logits[e]);
        float s = 0.f, ex[ED];
        for (int e = 0; e < ED; e++) { ex[e] = expf(logits[e] - mx); s += ex[e]; }
        int i1 = 0; float v1 = logits[0];
        for (int e = 1; e < ED; e++) if (logits[e] > v1) { v1 = logits[e]; i1 = e; }
        int i2 = -1; float v2 = -1e30f;
        for (int e = 0; e < ED; e++) if (e != i1 && logits[e] > v2) { v2 = logits[e]; i2 = e; }
        float w1 = ex[i1] / s, w2 = ex[i2] / s;
        int s1 = atomicAdd(&g_counts[i1], 1);
        if (s1 < CAPN) { g_slot_tok[i1 * CAPN + s1] = t; g_slot_w[i1 * CAPN + s1] = w1; }
        int s2 = atomicAdd(&g_counts[i2], 1);
        if (s2 < CAPN) { g_slot_tok[i2 * CAPN + s2] = t; g_slot_w[i2 * CAPN + s2] = w2; }
    }
}

// modes: 0 u_sh=x@ws_up  1 h_sh=silu(x@ws_gate)*u_sh  2 out=h_sh@ws_down
//        3 u_rt=gx@w_up  4 h_rt=silu(gx@w_gate)*u_rt  5 out+=w*(h_rt@w_down)
template <int MODE>
__global__ void __launch_bounds__(256)
moe_hmma(const float* __restrict__ Aarg, const float* __restrict__ Barg,
         float* __restrict__ outArg)
{
    constexpr bool ROUTED = (MODE >= 3);
    constexpr bool GATHER = (MODE == 3 || MODE == 4);
    constexpr int N = (MODE <= 1) ? ISD : (MODE == 2 || MODE == 5) ? HD : ID;
    constexpr int K = (MODE <= 1) ? HD : (MODE == 2) ? ISD : (MODE == 5) ? ID : HD;

    const int e = ROUTED ? blockIdx.z : 0;
    int M;
    if (ROUTED) { M = g_counts[e]; if (M > CAPN) M = CAPN; } else M = TT;
    const int bm = blockIdx.y * 128;
    if (bm >= M) return;
    const int bn = blockIdx.x * 128;

    const int tid = threadIdx.x, lane = tid & 31, warp = tid >> 5;
    const int wm = warp & 3, wn = warp >> 2;

    __shared__ int   s_tok[128];
    __shared__ float s_wt[128];
    extern __shared__ char smem_raw[];
    const uint32_t sb = smem_u32(smem_raw);

    if (ROUTED) {
        if (tid < 128) {
            int r = bm + tid;
            s_tok[tid] = (r < M) ? g_slot_tok[e * CAPN + r] : g_slot_tok[e * CAPN];
            s_wt[tid]  = (r < M) ? g_slot_w[e * CAPN + r]  : 0.f;
        }
        __syncthreads();
    }

    const float* Abase;
    if (MODE == 2)      Abase = g_h_shared;
    else if (MODE == 5) Abase = g_h_routed + (size_t)e * CAPN * ID;
    else                Abase = Aarg;
    const float* B = Barg + (ROUTED ? (size_t)e * HD * ID : (size_t)0);

    const int arow_i = tid >> 1;
    const int kq     = (tid & 1) * 16;
    const float* arow = GATHER ? Aarg + (size_t)s_tok[arow_i] * HD
                               : Abase + (size_t)(bm + arow_i) * K;
    const int krow = tid >> 3;
    const int nq   = (tid & 7) * 16;
    const float* brow = B + (size_t)krow * N + bn + nq;

    const uint32_t a_sts = (uint32_t)(arow_i * ASTRIDE_B + kq * 2);
    const uint32_t b_sts = (uint32_t)(krow * BSTRIDE_B + nq * 2);
    const uint32_t a_ld  = (uint32_t)((wm * 32 + (lane & 15)) * ASTRIDE_B + (lane >> 4) * 16);
    const uint32_t b_ld  = (uint32_t)((lane & 15) * BSTRIDE_B + (wn * 64 + (lane >> 4) * 8) * 2);

    float acc[2][8][4];
#pragma unroll
    for (int i = 0; i < 2; i++)
#pragma unroll
        for (int j = 0; j < 8; j++)
#pragma unroll
            for (int q = 0; q < 4; q++) acc[i][j][q] = 0.f;

    float4 pa[4], pb[4];
    auto ldg_stage = [&](int t) {
        const float* pA = arow + t * 32 + kq;
#pragma unroll
        for (int i = 0; i < 4; i++) pa[i] = *(const float4*)(pA + 4 * i);
        const float* pB = brow + (size_t)(t * 32) * N;
#pragma unroll
        for (int i = 0; i < 4; i++) pb[i] = *(const float4*)(pB + 4 * i);
    };
    auto cvt_sts = [&](int t) {
        uint32_t base = sb + (uint32_t)(t & 1) * STAGE;
        uint32_t h[8], l[8];
        cvt_hilo(pa[0].x, pa[0].y, h[0], l[0]); cvt_hilo(pa[0].z, pa[0].w, h[1], l[1]);
        cvt_hilo(pa[1].x, pa[1].y, h[2], l[2]); cvt_hilo(pa[1].z, pa[1].w, h[3], l[3]);
        cvt_hilo(pa[2].x, pa[2].y, h[4], l[4]); cvt_hilo(pa[2].z, pa[2].w, h[5], l[5]);
        cvt_hilo(pa[3].x, pa[3].y, h[6], l[6]); cvt_hilo(pa[3].z, pa[3].w, h[7], l[7]);
        sts128(base + AHI + a_sts,      h[0], h[1], h[2], h[3]);
        sts128(base + AHI + a_sts + 16, h[4], h[5], h[6], h[7]);
        sts128(base + ALO + a_sts,      l[0], l[1], l[2], l[3]);
        sts128(base + ALO + a_sts + 16, l[4], l[5], l[6], l[7]);
        cvt_hilo(pb[0].x, pb[0].y, h[0], l[0]); cvt_hilo(pb[0].z, pb[0].w, h[1], l[1]);
        cvt_hilo(pb[1].x, pb[1].y, h[2], l[2]); cvt_hilo(pb[1].z, pb[1].w, h[3], l[3]);
        cvt_hilo(pb[2].x, pb[2].y, h[4], l[4]); cvt_hilo(pb[2].z, pb[2].w, h[5], l[5]);
        cvt_hilo(pb[3].x, pb[3].y, h[6], l[6]); cvt_hilo(pb[3].z, pb[3].w, h[7], l[7]);
        sts128(base + BHI + b_sts,      h[0], h[1], h[2], h[3]);
        sts128(base + BHI + b_sts + 16, h[4], h[5], h[6], h[7]);
        sts128(base + BLO + b_sts,      l[0], l[1], l[2], l[3]);
        sts128(base + BLO + b_sts + 16, l[4], l[5], l[6], l[7]);
    };
    auto compute = [&](int t) {
        uint32_t base = sb + (uint32_t)(t & 1) * STAGE;
#pragma unroll
        for (int kt = 0; kt < 2; kt++) {
            uint32_t a_hi[2][4], a_lo[2][4];
            uint32_t ab = base + AHI + a_ld + kt * 32;
            LDSM_X4(a_hi[0], ab);
            LDSM_X4(a_hi[1], ab + 16 * ASTRIDE_B);
            uint32_t al = base + ALO + a_ld + kt * 32;
            LDSM_X4(a_lo[0], al);
            LDSM_X4(a_lo[1], al + 16 * ASTRIDE_B);
            uint32_t b_hi[8][2], b_lo[8][2];
            uint32_t bb = base + BHI + b_ld + kt * 16 * BSTRIDE_B;
            uint32_t bl = base + BLO + b_ld + kt * 16 * BSTRIDE_B;
#pragma unroll
            for (int nb = 0; nb < 4; nb++) {
                LDSM_X4T(b_hi[2 * nb][0], b_hi[2 * nb][1], b_hi[2 * nb + 1][0], b_hi[2 * nb + 1][1], bb + nb * 32);
                LDSM_X4T(b_lo[2 * nb][0], b_lo[2 * nb][1], b_lo[2 * nb + 1][0], b_lo[2 * nb + 1][1], bl + nb * 32);
            }
#pragma unroll
            for (int mf = 0; mf < 2; mf++)
#pragma unroll
                for (int nf = 0; nf < 8; nf++) {
                    MMA_BF16(acc[mf][nf], a_hi[mf], b_hi[nf][0], b_hi[nf][1]);
                    MMA_BF16(acc[mf][nf], a_hi[mf], b_lo[nf][0], b_lo[nf][1]);
                    MMA_BF16(acc[mf][nf], a_lo[mf], b_hi[nf][0], b_hi[nf][1]);
                }
        }
    };

    const int NT = K / 32;
    ldg_stage(0);
    cvt_sts(0);
    for (int t = 0; t < NT; t++) {
        if (t + 1 < NT) ldg_stage(t + 1);
        __syncthreads();
        compute(t);
        if (t + 1 < NT) cvt_sts(t + 1);
    }

#pragma unroll
    for (int mf = 0; mf < 2; mf++) {
#pragma unroll
        for (int nf = 0; nf < 8; nf++) {
            int n = bn + wn * 64 + nf * 8 + (lane & 3) * 2;
#pragma unroll
            for (int h = 0; h < 2; h++) {
                int ml = wm * 32 + mf * 16 + (lane >> 2) + h * 8;
                int m  = bm + ml;
                if (m < M) {
                    float d0 = acc[mf][nf][2 * h], d1 = acc[mf][nf][2 * h + 1];
                    if (MODE == 0) {
                        *(float2*)&g_u_shared[(size_t)m * ISD + n] = make_float2(d0, d1);
                    } else if (MODE == 1) {
                        float2 u = *(const float2*)&g_u_shared[(size_t)m * ISD + n];
                        float h0 = d0 / (1.f + expf(-d0)) * u.x;
                        float h1 = d1 / (1.f + expf(-d1)) * u.y;
                        *(float2*)&g_h_shared[(size_t)m * ISD + n] = make_float2(h0, h1);
                    } else if (MODE == 2) {
                        *(float2*)&outArg[(size_t)m * HD + n] = make_float2(d0, d1);
                    } else if (MODE == 3) {
                        *(float2*)&g_u_routed[((size_t)e * CAPN + m) * ID + n] = make_float2(d0, d1);
                    } else if (MODE == 4) {
                        float2 u = *(const float2*)&g_u_routed[((size_t)e * CAPN + m) * ID + n];
                        float h0 = d0 / (1.f + expf(-d0)) * u.x;
                        float h1 = d1 / (1.f + expf(-d1)) * u.y;
                        *(float2*)&g_h_routed[((size_t)e * CAPN + m) * ID + n] = make_float2(h0, h1);
                    } else {
                        int tok = s_tok[ml];
                        float wgt = s_wt[ml];
                        atomicAdd(&outArg[(size_t)tok * HD + n],     wgt * d0);
                        atomicAdd(&outArg[(size_t)tok * HD + n + 1], wgt * d1);
                    }
                }
            }
        }
    }
}

extern "C" void kernel_launch(void* const* d_in, const int* in_sizes, int n_in,
                              void* d_out, int out_size) {
    const float* x       = (const float*)d_in[0];
    const float* gate_w  = (const float*)d_in[1];
    const float* w_gate  = (const float*)d_in[2];
    const float* w_up    = (const float*)d_in[3];
    const float* w_down  = (const float*)d_in[4];
    const float* ws_gate = (const float*)d_in[5];
    const float* ws_up   = (const float*)d_in[6];
    const float* ws_down = (const float*)d_in[7];
    float* out = (float*)d_out;

    cudaFuncSetAttribute(moe_hmma<0>, cudaFuncAttributeMaxDynamicSharedMemorySize, DSMEM);
    cudaFuncSetAttribute(moe_hmma<1>, cudaFuncAttributeMaxDynamicSharedMemorySize, DSMEM);
    cudaFuncSetAttribute(moe_hmma<2>, cudaFuncAttributeMaxDynamicSharedMemorySize, DSMEM);
    cudaFuncSetAttribute(moe_hmma<3>, cudaFuncAttributeMaxDynamicSharedMemorySize, DSMEM);
    cudaFuncSetAttribute(moe_hmma<4>, cudaFuncAttributeMaxDynamicSharedMemorySize, DSMEM);
    cudaFuncSetAttribute(moe_hmma<5>, cudaFuncAttributeMaxDynamicSharedMemorySize, DSMEM);

    init_counts_kernel<<<1, 32>>>();
    router_kernel<<<TT, 512>>>(x, gate_w);

    moe_hmma<0><<<dim3(ISD / 128, TT / 128), 256, DSMEM>>>(x, ws_up, out);
    moe_hmma<1><<<dim3(ISD / 128, TT / 128), 256, DSMEM>>>(x, ws_gate, out);
    moe_hmma<2><<<dim3(HD / 128, TT / 128), 256, DSMEM>>>(x, ws_down, out);

    moe_hmma<3><<<dim3(ID / 128, CAPN / 128, ED), 256, DSMEM>>>(x, w_up, out);
    moe_hmma<4><<<dim3(ID / 128, CAPN / 128, ED), 256, DSMEM>>>(x, w_gate, out);
    moe_hmma<5><<<dim3(HD / 128, CAPN / 128, ED), 256, DSMEM>>>(x, w_down, out);
}